// round 1
// baseline (speedup 1.0000x reference)
#include <cuda_runtime.h>
#include <cstdint>

// Problem constants (fixed shapes for this problem)
#define NN 8192
#define BB 4
#define CC 256
#define MAXE 262144

// ---------------- scratch (__device__ globals; no allocation allowed) ------
__device__ int   g_deg[NN];
__device__ int   g_rowstart[NN + 1];
__device__ int   g_fill[NN];
__device__ int   g_col[MAXE];
__device__ float g_y[(size_t)BB * NN * CC];  // aggregated neighbor features, 32 MB
__device__ int   g_is64;                     // edge_index dtype flag

// ---------------- small helpers -------------------------------------------
__device__ __forceinline__ uint32_t f2tf32(float f) {
    uint32_t r;
    asm("cvt.rna.tf32.f32 %0, %1;" : "=r"(r) : "f"(f));
    return r;
}

__device__ __forceinline__ float gelu_exact(float v) {
    return 0.5f * v * (1.0f + erff(v * 0.70710678118654752f));
}

// ---------------- CSR build ------------------------------------------------
__global__ void k_zero() {
    int i = blockIdx.x * blockDim.x + threadIdx.x;
    if (i < NN) { g_deg[i] = 0; g_fill[i] = 0; }
}

// Detect whether edge_index is int64 or int32 on device.
// int64 little-endian values < 8192 => every odd 32-bit word is 0.
// int32 random values in [0,8192) => odd words are ~uniform, all-zero impossible.
__global__ void k_detect(const int* __restrict__ ei32) {
    __shared__ int anynz;
    if (threadIdx.x == 0) anynz = 0;
    __syncthreads();
    if (ei32[2 * threadIdx.x + 1] != 0) atomicOr(&anynz, 1);
    __syncthreads();
    if (threadIdx.x == 0) g_is64 = anynz ? 0 : 1;
}

__global__ void k_count(const void* __restrict__ ei, int E) {
    int e = blockIdx.x * blockDim.x + threadIdx.x;
    if (e >= E) return;
    int s;
    if (g_is64) s = (int)((const long long*)ei)[e];
    else        s = ((const int*)ei)[e];
    atomicAdd(&g_deg[s], 1);
}

// Exclusive prefix sum over g_deg[8192] -> g_rowstart. One block, 1024 threads x 8.
__global__ void k_scan() {
    __shared__ int tmp[1024];
    int tid = threadIdx.x;
    int local[8];
    int s = 0;
#pragma unroll
    for (int i = 0; i < 8; i++) { local[i] = s; s += g_deg[tid * 8 + i]; }
    tmp[tid] = s;
    __syncthreads();
    for (int off = 1; off < 1024; off <<= 1) {
        int v = (tid >= off) ? tmp[tid - off] : 0;
        __syncthreads();
        tmp[tid] += v;
        __syncthreads();
    }
    int excl = (tid == 0) ? 0 : tmp[tid - 1];
#pragma unroll
    for (int i = 0; i < 8; i++) g_rowstart[tid * 8 + i] = excl + local[i];
    if (tid == 1023) g_rowstart[NN] = excl + s;
}

__global__ void k_fill(const void* __restrict__ ei, int E) {
    int e = blockIdx.x * blockDim.x + threadIdx.x;
    if (e >= E) return;
    int s, d;
    if (g_is64) {
        s = (int)((const long long*)ei)[e];
        d = (int)((const long long*)ei)[(size_t)E + e];
    } else {
        s = ((const int*)ei)[e];
        d = ((const int*)ei)[(size_t)E + e];
    }
    int p = g_rowstart[s] + atomicAdd(&g_fill[s], 1);
    g_col[p] = d;
}

// ---------------- sparse aggregation: y = A_hat @ x ------------------------
// One block per (node, batch); 256 threads = channels. Gathers neighbor rows
// (coalesced 1KB reads, L2-resident) and averages including the self loop.
__global__ void k_agg(const float* __restrict__ x) {
    __shared__ int scol[256];
    const int i = blockIdx.x;   // node
    const int b = blockIdx.y;   // batch
    const int c = threadIdx.x;  // channel
    const float* xb = x + (size_t)b * NN * CC;

    const int s = g_rowstart[i];
    const int e = g_rowstart[i + 1];

    float a0 = xb[(size_t)i * CC + c];  // self loop
    float a1 = 0.f, a2 = 0.f, a3 = 0.f;

    for (int p0 = s; p0 < e; p0 += 256) {
        int np = min(256, e - p0);
        __syncthreads();
        if (threadIdx.x < np) scol[threadIdx.x] = g_col[p0 + threadIdx.x];
        __syncthreads();
        int q = 0;
        for (; q + 4 <= np; q += 4) {
            a0 += __ldg(&xb[(size_t)scol[q + 0] * CC + c]);
            a1 += __ldg(&xb[(size_t)scol[q + 1] * CC + c]);
            a2 += __ldg(&xb[(size_t)scol[q + 2] * CC + c]);
            a3 += __ldg(&xb[(size_t)scol[q + 3] * CC + c]);
        }
        for (; q < np; q++) a0 += __ldg(&xb[(size_t)scol[q] * CC + c]);
    }
    float inv = 1.0f / (float)(e - s + 1);
    g_y[((size_t)b * NN + i) * CC + c] = (a0 + a1 + a2 + a3) * inv;
}

// ---------------- fused GEMM + bias + GELU ---------------------------------
// out[m,n] = gelu( x[m,:]@W_self[:,n] + y[m,:]@W_neigh[:,n] + b_self[n]+b_neigh[n] )
// Treated as a single [32768 x 512] * [512 x 256] tf32 tensor-core GEMM.
// CTA tile 128x128, K-chunk 32, 8 warps (4M x 2N), warp tile 32x64,
// mma.sync.m16n8k8.tf32. Padded smem layouts -> conflict-free fragment loads.
__global__ __launch_bounds__(256) void k_gemm(
    const float* __restrict__ x,
    const float* __restrict__ Wself, const float* __restrict__ bself,
    const float* __restrict__ Wneigh, const float* __restrict__ bneigh,
    float* __restrict__ out)
{
    __shared__ uint32_t As[128][36];   // stride 36: 4g+t4 -> conflict-free
    __shared__ uint32_t Bs[32][136];   // stride 136: 8t4+g -> conflict-free
    __shared__ float sBias[128];

    const int tid  = threadIdx.x;
    const int lane = tid & 31;
    const int warp = tid >> 5;
    const int wm   = warp & 3;    // 0..3 (M)
    const int wn   = warp >> 2;   // 0..1 (N)
    const int g    = lane >> 2;   // 0..7
    const int t4   = lane & 3;    // 0..3

    const int m0 = blockIdx.x * 128;
    const int n0 = blockIdx.y * 128;

    if (tid < 128) sBias[tid] = bself[n0 + tid] + bneigh[n0 + tid];

    float acc[2][8][4];
#pragma unroll
    for (int mi = 0; mi < 2; mi++)
#pragma unroll
        for (int ni = 0; ni < 8; ni++)
#pragma unroll
            for (int r = 0; r < 4; r++) acc[mi][ni][r] = 0.f;

    const int ar = tid >> 3;            // 0..31  (A row within pass)
    const int ac = (tid & 7) * 4;       // 0..28  (A col, float4)
    const int br = tid >> 5;            // 0..7   (B row within pass)
    const int bc = (tid & 31) * 4;      // 0..124 (B col, float4)

    for (int ki = 0; ki < 16; ++ki) {
        const int kc = (ki & 7) * 32;
        const float* Ab = (ki < 8) ? x : (const float*)g_y;
        const float* Bb = (ki < 8) ? Wself : Wneigh;

#pragma unroll
        for (int r = ar; r < 128; r += 32) {
            float4 v = *(const float4*)&Ab[(size_t)(m0 + r) * 256 + kc + ac];
            As[r][ac + 0] = f2tf32(v.x);
            As[r][ac + 1] = f2tf32(v.y);
            As[r][ac + 2] = f2tf32(v.z);
            As[r][ac + 3] = f2tf32(v.w);
        }
#pragma unroll
        for (int r = br; r < 32; r += 8) {
            float4 v = *(const float4*)&Bb[(size_t)(kc + r) * 256 + n0 + bc];
            Bs[r][bc + 0] = f2tf32(v.x);
            Bs[r][bc + 1] = f2tf32(v.y);
            Bs[r][bc + 2] = f2tf32(v.z);
            Bs[r][bc + 3] = f2tf32(v.w);
        }
        __syncthreads();

#pragma unroll
        for (int kk = 0; kk < 32; kk += 8) {
            uint32_t a[2][4], bf[8][2];
#pragma unroll
            for (int mi = 0; mi < 2; mi++) {
                int row = wm * 32 + mi * 16 + g;
                a[mi][0] = As[row][kk + t4];
                a[mi][1] = As[row + 8][kk + t4];
                a[mi][2] = As[row][kk + t4 + 4];
                a[mi][3] = As[row + 8][kk + t4 + 4];
            }
#pragma unroll
            for (int ni = 0; ni < 8; ni++) {
                int cl = wn * 64 + ni * 8 + g;
                bf[ni][0] = Bs[kk + t4][cl];
                bf[ni][1] = Bs[kk + t4 + 4][cl];
            }
#pragma unroll
            for (int mi = 0; mi < 2; mi++)
#pragma unroll
                for (int ni = 0; ni < 8; ni++)
                    asm volatile(
                        "mma.sync.aligned.m16n8k8.row.col.f32.tf32.tf32.f32 "
                        "{%0,%1,%2,%3}, {%4,%5,%6,%7}, {%8,%9}, {%0,%1,%2,%3};"
                        : "+f"(acc[mi][ni][0]), "+f"(acc[mi][ni][1]),
                          "+f"(acc[mi][ni][2]), "+f"(acc[mi][ni][3])
                        : "r"(a[mi][0]), "r"(a[mi][1]), "r"(a[mi][2]), "r"(a[mi][3]),
                          "r"(bf[ni][0]), "r"(bf[ni][1]));
        }
        __syncthreads();
    }

    // Epilogue: bias + exact GELU, write fp32 output.
#pragma unroll
    for (int mi = 0; mi < 2; mi++) {
        int row = m0 + wm * 32 + mi * 16 + g;
#pragma unroll
        for (int ni = 0; ni < 8; ni++) {
            int cl  = wn * 64 + ni * 8 + t4 * 2;
            int col = n0 + cl;
            float b0v = sBias[cl], b1v = sBias[cl + 1];
            out[(size_t)row * 256 + col]           = gelu_exact(acc[mi][ni][0] + b0v);
            out[(size_t)row * 256 + col + 1]       = gelu_exact(acc[mi][ni][1] + b1v);
            out[(size_t)(row + 8) * 256 + col]     = gelu_exact(acc[mi][ni][2] + b0v);
            out[(size_t)(row + 8) * 256 + col + 1] = gelu_exact(acc[mi][ni][3] + b1v);
        }
    }
}

// ---------------- launch ----------------------------------------------------
extern "C" void kernel_launch(void* const* d_in, const int* in_sizes, int n_in,
                              void* d_out, int out_size) {
    const float* x      = (const float*)d_in[0];
    const void*  ei     = d_in[1];
    const float* Wself  = (const float*)d_in[2];
    const float* bself  = (const float*)d_in[3];
    const float* Wneigh = (const float*)d_in[4];
    const float* bneigh = (const float*)d_in[5];
    float* out = (float*)d_out;

    int E = in_sizes[1] / 2;
    if (E > MAXE) E = MAXE;

    k_zero<<<(NN + 255) / 256, 256>>>();
    k_detect<<<1, 256>>>((const int*)ei);
    k_count<<<(E + 255) / 256, 256>>>(ei, E);
    k_scan<<<1, 1024>>>();
    k_fill<<<(E + 255) / 256, 256>>>(ei, E);

    dim3 gagg(NN, BB);
    k_agg<<<gagg, 256>>>(x);

    dim3 ggemm((BB * NN) / 128, 256 / 128);
    k_gemm<<<ggemm, 256>>>(x, Wself, bself, Wneigh, bneigh, out);
}

// round 7
// speedup vs baseline: 1.2297x; 1.2297x over previous
#include <cuda_runtime.h>
#include <cstdint>

#define NN 8192
#define BB 4
#define CC 256
#define MAXE 262144

// ---------------- scratch --------------------------------------------------
__device__ __align__(16) int   g_deg[NN];
__device__ __align__(16) int   g_rowstart[NN + 1];
__device__ int   g_fill[NN];
__device__ int   g_col[MAXE];
__device__ __align__(16) float g_y[(size_t)BB * NN * CC];
__device__ int   g_is64;

// ---------------- helpers --------------------------------------------------
__device__ __forceinline__ uint32_t f2tf32(float f) {
    uint32_t r;
    asm("cvt.rna.tf32.f32 %0, %1;" : "=r"(r) : "f"(f));
    return r;
}
__device__ __forceinline__ float gelu_exact(float v) {
    return 0.5f * v * (1.0f + erff(v * 0.70710678118654752f));
}

// ---------------- init: zero counters + dtype detect ------------------------
// int64 edge values < 8192 => every odd 32-bit word is 0; int32 random => not.
__global__ void k_zero(const int* __restrict__ ei32) {
    int i = blockIdx.x * blockDim.x + threadIdx.x;
    if (i < NN) { g_deg[i] = 0; g_fill[i] = 0; }
    if (blockIdx.x == 0) {
        __shared__ int anynz;
        if (threadIdx.x == 0) anynz = 0;
        __syncthreads();
        if (ei32[2 * threadIdx.x + 1] != 0) atomicOr(&anynz, 1);
        __syncthreads();
        if (threadIdx.x == 0) g_is64 = anynz ? 0 : 1;
    }
}

__global__ void k_count(const void* __restrict__ ei, int E) {
    int e = blockIdx.x * blockDim.x + threadIdx.x;
    if (e >= E) return;
    int s = g_is64 ? (int)((const long long*)ei)[e] : ((const int*)ei)[e];
    atomicAdd(&g_deg[s], 1);
}

// Exclusive scan of g_deg[8192] via shfl warp scans. 1024 threads x 8 elems.
__global__ void k_scan() {
    __shared__ int wsum[32];
    const int tid  = threadIdx.x;
    const int lane = tid & 31;
    const int wid  = tid >> 5;

    int4 d0 = *(const int4*)&g_deg[tid * 8];
    int4 d1 = *(const int4*)&g_deg[tid * 8 + 4];
    int l0 = 0;
    int l1 = l0 + d0.x;
    int l2 = l1 + d0.y;
    int l3 = l2 + d0.z;
    int l4 = l3 + d0.w;
    int l5 = l4 + d1.x;
    int l6 = l5 + d1.y;
    int l7 = l6 + d1.z;
    int s  = l7 + d1.w;

    int inc = s;
#pragma unroll
    for (int off = 1; off < 32; off <<= 1) {
        int v = __shfl_up_sync(0xffffffff, inc, off);
        if (lane >= off) inc += v;
    }
    if (lane == 31) wsum[wid] = inc;
    __syncthreads();
    if (wid == 0) {
        int w = wsum[lane];
        int wi = w;
#pragma unroll
        for (int off = 1; off < 32; off <<= 1) {
            int v = __shfl_up_sync(0xffffffff, wi, off);
            if (lane >= off) wi += v;
        }
        wsum[lane] = wi - w;  // exclusive
    }
    __syncthreads();
    int excl = (inc - s) + wsum[wid];

    int4 o0 = make_int4(excl + l0, excl + l1, excl + l2, excl + l3);
    int4 o1 = make_int4(excl + l4, excl + l5, excl + l6, excl + l7);
    *(int4*)&g_rowstart[tid * 8]     = o0;
    *(int4*)&g_rowstart[tid * 8 + 4] = o1;
    if (tid == 1023) g_rowstart[NN] = excl + s;
}

__global__ void k_fill(const void* __restrict__ ei, int E) {
    int e = blockIdx.x * blockDim.x + threadIdx.x;
    if (e >= E) return;
    int s, d;
    if (g_is64) {
        s = (int)((const long long*)ei)[e];
        d = (int)((const long long*)ei)[(size_t)E + e];
    } else {
        s = ((const int*)ei)[e];
        d = ((const int*)ei)[(size_t)E + e];
    }
    int p = g_rowstart[s] + atomicAdd(&g_fill[s], 1);
    g_col[p] = d;
}

// ---------------- aggregation: y = A_hat @ x (all batches per block) --------
// One block per node, 256 threads = (batch 0..3) x (float4 group 0..63).
// Each thread owns (b, c4) fully -> serial neighbor loop, LDG.128, MLP=4.
__device__ __forceinline__ void f4add(float4& a, const float4 b) {
    a.x += b.x; a.y += b.y; a.z += b.z; a.w += b.w;
}

__global__ __launch_bounds__(256) void k_agg(const float* __restrict__ x) {
    __shared__ int scol[128];
    const int i  = blockIdx.x;
    const int b  = threadIdx.x >> 6;
    const int c4 = threadIdx.x & 63;
    const float4* xb = (const float4*)x + (size_t)b * NN * 64;

    const int s = g_rowstart[i];
    const int e = g_rowstart[i + 1];

    float4 a0 = __ldg(&xb[(size_t)i * 64 + c4]);  // self loop
    float4 a1 = make_float4(0.f, 0.f, 0.f, 0.f);
    float4 a2 = a1, a3 = a1;

    for (int p0 = s; p0 < e; p0 += 128) {
        int np = min(128, e - p0);
        __syncthreads();
        if (threadIdx.x < np) scol[threadIdx.x] = g_col[p0 + threadIdx.x];
        __syncthreads();
        int q = 0;
        for (; q + 4 <= np; q += 4) {
            f4add(a0, __ldg(&xb[(size_t)scol[q + 0] * 64 + c4]));
            f4add(a1, __ldg(&xb[(size_t)scol[q + 1] * 64 + c4]));
            f4add(a2, __ldg(&xb[(size_t)scol[q + 2] * 64 + c4]));
            f4add(a3, __ldg(&xb[(size_t)scol[q + 3] * 64 + c4]));
        }
        for (; q < np; q++)
            f4add(a0, __ldg(&xb[(size_t)scol[q] * 64 + c4]));
    }
    float inv = 1.0f / (float)(e - s + 1);
    f4add(a0, a1); f4add(a2, a3); f4add(a0, a2);
    float4 r = make_float4(a0.x * inv, a0.y * inv, a0.z * inv, a0.w * inv);
    ((float4*)g_y)[((size_t)b * NN + i) * 64 + c4] = r;
}

// ---------------- fused GEMM + bias + GELU ---------------------------------
// [32768 x 512] * [512 x 256] tf32 GEMM (K=512 = x|y with stacked weights).
// CTA tile 128x128, 512 threads (16 warps, 4x4 grid of 32x32 warp tiles),
// Kc=32, register-prefetch pipelining: stage ki+1 global loads issue before
// stage ki compute so L2 latency hides under the MMAs.
__global__ __launch_bounds__(512) void k_gemm(
    const float* __restrict__ x,
    const float* __restrict__ Wself, const float* __restrict__ bself,
    const float* __restrict__ Wneigh, const float* __restrict__ bneigh,
    float* __restrict__ out)
{
    __shared__ uint32_t As[128][36];   // bank = (4g + t4): conflict-free frags
    __shared__ uint32_t Bs[32][136];   // bank = (8t4 + g): conflict-free frags
    __shared__ float sBias[128];

    const int tid  = threadIdx.x;
    const int lane = tid & 31;
    const int warp = tid >> 5;
    const int wm   = warp & 3;    // 0..3 (M)
    const int wn   = warp >> 2;   // 0..3 (N)
    const int g    = lane >> 2;
    const int t4   = lane & 3;

    const int m0 = blockIdx.x * 128;
    const int n0 = blockIdx.y * 128;

    if (tid < 128) sBias[tid] = bself[n0 + tid] + bneigh[n0 + tid];

    float acc[2][4][4];
#pragma unroll
    for (int mi = 0; mi < 2; mi++)
#pragma unroll
        for (int ni = 0; ni < 4; ni++)
#pragma unroll
            for (int r = 0; r < 4; r++) acc[mi][ni][r] = 0.f;

    const int ar = tid >> 3;          // 0..63, second slot ar+64
    const int ac = (tid & 7) * 4;
    const int br = tid >> 5;          // 0..15, second slot br+16
    const int bc = (tid & 31) * 4;

    float4 pa0, pa1, pb0, pb1;

#define GEMM_ISSUE(KI)                                                        \
    {                                                                         \
        const int kc = ((KI) & 7) * 32;                                       \
        const float* Ab = ((KI) < 8) ? x : (const float*)g_y;                 \
        const float* Bb = ((KI) < 8) ? Wself : Wneigh;                        \
        pa0 = *(const float4*)&Ab[(size_t)(m0 + ar) * 256 + kc + ac];         \
        pa1 = *(const float4*)&Ab[(size_t)(m0 + ar + 64) * 256 + kc + ac];    \
        pb0 = *(const float4*)&Bb[(size_t)(kc + br) * 256 + n0 + bc];         \
        pb1 = *(const float4*)&Bb[(size_t)(kc + br + 16) * 256 + n0 + bc];    \
    }

#define GEMM_STORE()                                                          \
    {                                                                         \
        As[ar][ac + 0] = f2tf32(pa0.x); As[ar][ac + 1] = f2tf32(pa0.y);       \
        As[ar][ac + 2] = f2tf32(pa0.z); As[ar][ac + 3] = f2tf32(pa0.w);       \
        As[ar + 64][ac + 0] = f2tf32(pa1.x); As[ar + 64][ac + 1] = f2tf32(pa1.y); \
        As[ar + 64][ac + 2] = f2tf32(pa1.z); As[ar + 64][ac + 3] = f2tf32(pa1.w); \
        Bs[br][bc + 0] = f2tf32(pb0.x); Bs[br][bc + 1] = f2tf32(pb0.y);       \
        Bs[br][bc + 2] = f2tf32(pb0.z); Bs[br][bc + 3] = f2tf32(pb0.w);       \
        Bs[br + 16][bc + 0] = f2tf32(pb1.x); Bs[br + 16][bc + 1] = f2tf32(pb1.y); \
        Bs[br + 16][bc + 2] = f2tf32(pb1.z); Bs[br + 16][bc + 3] = f2tf32(pb1.w); \
    }

    GEMM_ISSUE(0);
    GEMM_STORE();
    __syncthreads();

    for (int ki = 0; ki < 16; ++ki) {
        if (ki < 15) GEMM_ISSUE(ki + 1);

#pragma unroll
        for (int kk = 0; kk < 32; kk += 8) {
            uint32_t a[2][4], bf[4][2];
#pragma unroll
            for (int mi = 0; mi < 2; mi++) {
                int row = wm * 32 + mi * 16 + g;
                a[mi][0] = As[row][kk + t4];
                a[mi][1] = As[row + 8][kk + t4];
                a[mi][2] = As[row][kk + t4 + 4];
                a[mi][3] = As[row + 8][kk + t4 + 4];
            }
#pragma unroll
            for (int ni = 0; ni < 4; ni++) {
                int cl = wn * 32 + ni * 8 + g;
                bf[ni][0] = Bs[kk + t4][cl];
                bf[ni][1] = Bs[kk + t4 + 4][cl];
            }
#pragma unroll
            for (int mi = 0; mi < 2; mi++)
#pragma unroll
                for (int ni = 0; ni < 4; ni++)
                    asm volatile(
                        "mma.sync.aligned.m16n8k8.row.col.f32.tf32.tf32.f32 "
                        "{%0,%1,%2,%3}, {%4,%5,%6,%7}, {%8,%9}, {%0,%1,%2,%3};"
                        : "+f"(acc[mi][ni][0]), "+f"(acc[mi][ni][1]),
                          "+f"(acc[mi][ni][2]), "+f"(acc[mi][ni][3])
                        : "r"(a[mi][0]), "r"(a[mi][1]), "r"(a[mi][2]), "r"(a[mi][3]),
                          "r"(bf[ni][0]), "r"(bf[ni][1]));
        }
        __syncthreads();
        if (ki < 15) {
            GEMM_STORE();
            __syncthreads();
        }
    }

    // epilogue: bias + exact GELU
#pragma unroll
    for (int mi = 0; mi < 2; mi++) {
        int row = m0 + wm * 32 + mi * 16 + g;
#pragma unroll
        for (int ni = 0; ni < 4; ni++) {
            int cl  = wn * 32 + ni * 8 + t4 * 2;
            int col = n0 + cl;
            float b0v = sBias[cl], b1v = sBias[cl + 1];
            float2 r0 = make_float2(gelu_exact(acc[mi][ni][0] + b0v),
                                    gelu_exact(acc[mi][ni][1] + b1v));
            float2 r1 = make_float2(gelu_exact(acc[mi][ni][2] + b0v),
                                    gelu_exact(acc[mi][ni][3] + b1v));
            *(float2*)&out[(size_t)row * 256 + col]       = r0;
            *(float2*)&out[(size_t)(row + 8) * 256 + col] = r1;
        }
    }
}

// ---------------- launch ----------------------------------------------------
extern "C" void kernel_launch(void* const* d_in, const int* in_sizes, int n_in,
                              void* d_out, int out_size) {
    const float* x      = (const float*)d_in[0];
    const void*  ei     = d_in[1];
    const float* Wself  = (const float*)d_in[2];
    const float* bself  = (const float*)d_in[3];
    const float* Wneigh = (const float*)d_in[4];
    const float* bneigh = (const float*)d_in[5];
    float* out = (float*)d_out;

    int E = in_sizes[1] / 2;
    if (E > MAXE) E = MAXE;

    k_zero<<<(NN + 255) / 256, 256>>>((const int*)ei);
    k_count<<<(E + 255) / 256, 256>>>(ei, E);
    k_scan<<<1, 1024>>>();
    k_fill<<<(E + 255) / 256, 256>>>(ei, E);

    k_agg<<<NN, 256>>>(x);

    dim3 ggemm((BB * NN) / 128, CC / 128);
    k_gemm<<<ggemm, 512>>>(x, Wself, bself, Wneigh, bneigh, out);
}